// round 9
// baseline (speedup 1.0000x reference)
#include <cuda_runtime.h>
#include <math.h>

// ---------------------------------------------------------------------------
// TextEmbedderLETS on GB300 — R9: SPLITS 21 -> 6.
//   Insight from R4..R8: any re-read of the partial buffer costs ~2.2us/MB
//   plus a constant, regardless of protocol (separate kernel or in-kernel
//   finisher). So shrink the buffer: 6 z-splits -> 0.96MB partials, finisher
//   reads 6 values/thread from hot L2. 240 stream CTAs (2/SM) still saturate
//   HBM: per-warp MLP 8 x 512B x ~2000 warps >> required ~4MB in flight.
// ---------------------------------------------------------------------------

#define BD 256
#define B_SZ 8
#define C_SZ 7
#define T_SZ 45
#define D_SZ 5120
#define D4_SZ (D_SZ / 4)          // 1280
#define S_SZ 4096
#define SPLITS 6
#define SERIES_CTAS (D_SZ / BD)           // 20
#define STREAM_CTAS (5 * B_SZ * SPLITS)   // 240
#define TOTAL_CTAS (SERIES_CTAS + STREAM_CTAS) // 260 <= 296 (148*2): one wave
#define N_GROUPS (5 * B_SZ)               // 40

__device__ float4   g_part[SPLITS * B_SZ * D4_SZ];    // partial sums (0.96 MB)
__device__ float    g_emb [B_SZ * D_SZ];              // un-normalized projection
__device__ float    g_ssq_part[SERIES_CTAS * B_SZ];   // per-CTA per-batch sumsq
__device__ unsigned g_cnt[N_GROUPS];                  // per-group arrival counters
__device__ unsigned g_series_done;                    // == 20 when series done
__device__ unsigned g_fin;                            // finisher count (reset)

__device__ __forceinline__ unsigned atom_add_acqrel_gpu(unsigned* p, unsigned v) {
    unsigned old;
    asm volatile("atom.add.acq_rel.gpu.u32 %0, [%1], %2;"
                 : "=r"(old) : "l"(p), "r"(v) : "memory");
    return old;
}
__device__ __forceinline__ unsigned ld_acquire_gpu(const unsigned* p) {
    unsigned v;
    asm volatile("ld.acquire.gpu.u32 %0, [%1];" : "=r"(v) : "l"(p) : "memory");
    return v;
}

__global__ __launch_bounds__(BD, 2) void fused_kernel(
    const float* __restrict__ hs,
    const float* __restrict__ x,
    const float* __restrict__ W,
    const float* __restrict__ bias,
    float* __restrict__ out_fused,
    float* __restrict__ out_xnorm)
{
    const int cta = blockIdx.x;
    const int tid = threadIdx.x;

    if (cta < SERIES_CTAS) {
        // ================= series branch (20 CTAs) ==========================
        const int sid = cta;
        const int d   = sid * BD + tid;

        __shared__ float sx[B_SZ * C_SZ * T_SZ];
        __shared__ float smn[B_SZ * C_SZ], smx[B_SZ * C_SZ];
        __shared__ float s_sm[B_SZ * T_SZ];
        __shared__ float sred[8][B_SZ];

        const int TOT = B_SZ * C_SZ * T_SZ;       // 2520
        for (int i = tid; i < TOT; i += BD) sx[i] = x[i];
        __syncthreads();

        if (tid < B_SZ * C_SZ) {
            const float* row = sx + tid * T_SZ;
            float mn = row[0], mx = row[0];
            #pragma unroll
            for (int t = 1; t < T_SZ; t++) {
                float v = row[t];
                mn = fminf(mn, v); mx = fmaxf(mx, v);
            }
            smn[tid] = mn; smx[tid] = mx;
        }
        __syncthreads();

        if (sid == 0) {
            for (int i = tid; i < TOT; i += BD) {
                int bc = i / T_SZ;
                float v = sx[i], mn = smn[bc], mx = smx[bc];
                out_xnorm[i] = (mx > mn) ? (v - mn) / (mx - mn) : v;
            }
        }

        for (int i = tid; i < B_SZ * T_SZ; i += BD) {
            int b = i / T_SZ, t = i % T_SZ;
            float s = 0.f;
            #pragma unroll
            for (int c = 0; c < C_SZ; c++)
                s += sx[(b * C_SZ + c) * T_SZ + t];
            s_sm[i] = s * (1.0f / (float)C_SZ);
        }
        __syncthreads();

        const float bv = bias[d];
        const int warp = tid >> 5, lane = tid & 31;

        #pragma unroll
        for (int g = 0; g < 2; g++) {
            float acc0 = bv, acc1 = bv, acc2 = bv, acc3 = bv;
            const float* m0 = s_sm + (g * 4 + 0) * T_SZ;
            const float* m1 = s_sm + (g * 4 + 1) * T_SZ;
            const float* m2 = s_sm + (g * 4 + 2) * T_SZ;
            const float* m3 = s_sm + (g * 4 + 3) * T_SZ;
            #pragma unroll
            for (int t = 0; t < T_SZ; t++) {
                const float w = W[(size_t)t * D_SZ + d];
                acc0 = fmaf(m0[t], w, acc0);
                acc1 = fmaf(m1[t], w, acc1);
                acc2 = fmaf(m2[t], w, acc2);
                acc3 = fmaf(m3[t], w, acc3);
            }
            g_emb[(size_t)(g * 4 + 0) * D_SZ + d] = acc0;
            g_emb[(size_t)(g * 4 + 1) * D_SZ + d] = acc1;
            g_emb[(size_t)(g * 4 + 2) * D_SZ + d] = acc2;
            g_emb[(size_t)(g * 4 + 3) * D_SZ + d] = acc3;

            const float sq[4] = {acc0 * acc0, acc1 * acc1, acc2 * acc2, acc3 * acc3};
            #pragma unroll
            for (int j = 0; j < 4; j++) {
                float v = sq[j];
                #pragma unroll
                for (int off = 16; off; off >>= 1)
                    v += __shfl_xor_sync(0xffffffffu, v, off);
                if (lane == 0) sred[warp][g * 4 + j] = v;
            }
            __syncthreads();
            if (tid < 4) {
                int b = g * 4 + tid;
                float tot = 0.f;
                #pragma unroll
                for (int w2 = 0; w2 < 8; w2++) tot += sred[w2][b];
                g_ssq_part[sid * B_SZ + b] = tot;
            }
            __syncthreads();
        }

        if (tid == 0) atom_add_acqrel_gpu(&g_series_done, 1u);
    } else {
        // ================= streaming CTAs (240) =============================
        const int scta   = cta - SERIES_CTAS;
        const int dchunk = scta % 5;
        const int b      = (scta / 5) % B_SZ;
        const int z      = scta / (5 * B_SZ);
        const int d4     = dchunk * BD + tid;
        const int group  = b * 5 + dchunk;

        const int s0 = (int)(((long long)z       * S_SZ) / SPLITS);
        const int s1 = (int)(((long long)(z + 1) * S_SZ) / SPLITS);
        const int rows = s1 - s0;                 // 682 or 683

        const float4* p = reinterpret_cast<const float4*>(hs)
                        + (size_t)b * S_SZ * D4_SZ + (size_t)s0 * D4_SZ + d4;

        float4 a0 = make_float4(0.f, 0.f, 0.f, 0.f);
        float4 a1 = make_float4(0.f, 0.f, 0.f, 0.f);
        float4 a2 = make_float4(0.f, 0.f, 0.f, 0.f);
        float4 a3 = make_float4(0.f, 0.f, 0.f, 0.f);

        int r = 0;
        #pragma unroll 2
        for (; r + 3 < rows; r += 4) {
            float4 v0 = __ldcs(p + (size_t)(r + 0) * D4_SZ);
            float4 v1 = __ldcs(p + (size_t)(r + 1) * D4_SZ);
            float4 v2 = __ldcs(p + (size_t)(r + 2) * D4_SZ);
            float4 v3 = __ldcs(p + (size_t)(r + 3) * D4_SZ);
            a0.x += v0.x; a0.y += v0.y; a0.z += v0.z; a0.w += v0.w;
            a1.x += v1.x; a1.y += v1.y; a1.z += v1.z; a1.w += v1.w;
            a2.x += v2.x; a2.y += v2.y; a2.z += v2.z; a2.w += v2.w;
            a3.x += v3.x; a3.y += v3.y; a3.z += v3.z; a3.w += v3.w;
        }
        for (; r < rows; r++) {
            float4 v = __ldcs(p + (size_t)r * D4_SZ);
            a0.x += v.x; a0.y += v.y; a0.z += v.z; a0.w += v.w;
        }

        float4 out;
        out.x = (a0.x + a1.x) + (a2.x + a3.x);
        out.y = (a0.y + a1.y) + (a2.y + a3.y);
        out.z = (a0.z + a1.z) + (a2.z + a3.z);
        out.w = (a0.w + a1.w) + (a2.w + a3.w);
        g_part[((size_t)z * B_SZ + b) * D4_SZ + d4] = out;

        // arrival: intra-CTA order + release-bump by thread 0
        __shared__ bool s_last;
        __syncthreads();
        if (tid == 0) {
            unsigned old = atom_add_acqrel_gpu(&g_cnt[group], 1u);
            s_last = (old == SPLITS - 1);
        }
        __syncthreads();

        if (s_last) {
            // ---- finisher: reduce 6 partials for this (b, dchunk) ----------
            __shared__ float s_inv;
            if (tid == 0) {
                while (ld_acquire_gpu(&g_series_done) < SERIES_CTAS)
                    __nanosleep(64);
                float ssq = 0.f;
                #pragma unroll
                for (int s = 0; s < SERIES_CTAS; s++)
                    ssq += __ldcg(&g_ssq_part[s * B_SZ + b]);
                s_inv = 1.0f / fmaxf(sqrtf(ssq), 1e-12f);
            }
            __syncthreads();

            const float4* gp = g_part + (size_t)b * D4_SZ + d4;
            float4 acc = make_float4(0.f, 0.f, 0.f, 0.f);
            #pragma unroll
            for (int zz = 0; zz < SPLITS; zz++) {
                float4 v = __ldcg(gp + (size_t)zz * (B_SZ * D4_SZ));
                acc.x += v.x; acc.y += v.y; acc.z += v.z; acc.w += v.w;
            }

            const float inv  = s_inv;
            const float invS = 1.0f / (float)S_SZ;
            const float* e = g_emb + (size_t)b * D_SZ + (size_t)d4 * 4;
            float e0 = __ldcg(e + 0), e1 = __ldcg(e + 1);
            float e2 = __ldcg(e + 2), e3 = __ldcg(e + 3);

            float4 o;
            o.x = fmaf(e0, inv, acc.x * invS);
            o.y = fmaf(e1, inv, acc.y * invS);
            o.z = fmaf(e2, inv, acc.z * invS);
            o.w = fmaf(e3, inv, acc.w * invS);
            reinterpret_cast<float4*>(out_fused)[(size_t)b * D4_SZ + d4] = o;

            // reset for next graph replay (kernel boundary orders visibility)
            __syncthreads();
            if (tid == 0) {
                g_cnt[group] = 0u;
                unsigned f = atom_add_acqrel_gpu(&g_fin, 1u);
                if (f == N_GROUPS - 1) {      // globally last finisher
                    g_series_done = 0u;
                    g_fin = 0u;
                }
            }
        }
    }
}

// ============================================================================
extern "C" void kernel_launch(void* const* d_in, const int* in_sizes, int n_in,
                              void* d_out, int out_size)
{
    const float* x    = (const float*)d_in[0];
    const float* hs   = (const float*)d_in[1];
    const float* W    = (const float*)d_in[2];
    const float* bias = (const float*)d_in[3];

    float* out_fused = (float*)d_out;                       // [B, D]
    float* out_xnorm = (float*)d_out + (size_t)B_SZ * D_SZ; // [B, C, T]

    fused_kernel<<<TOTAL_CTAS, BD>>>(hs, x, W, bias, out_fused, out_xnorm);
}

// round 10
// speedup vs baseline: 1.0344x; 1.0344x over previous
#include <cuda_runtime.h>
#include <math.h>

// ---------------------------------------------------------------------------
// TextEmbedderLETS on GB300 — R10: R8 + intra-group WORK STEALING.
//   R9 falsifier fired: <=2 CTAs/SM cannot hold BW -> back to 860 CTAs @6/SM.
//   R4-R8 ledger: all tail schemes cost ~7us ~= CTA finish-time spread
//   (spr_max ~1.1 on MLP-heavy streams). Fix: 21 CTAs per (b,dchunk) group
//   steal 64-row chunks from a group counter -> spread collapses to ~1 chunk.
// ---------------------------------------------------------------------------

#define BD 256
#define B_SZ 8
#define C_SZ 7
#define T_SZ 45
#define D_SZ 5120
#define D4_SZ (D_SZ / 4)          // 1280
#define S_SZ 4096
#define SPLITS 21                 // CTAs per group (partial slots)
#define CHUNK_ROWS 64
#define N_CHUNKS (S_SZ / CHUNK_ROWS)      // 64 chunks per group
#define SERIES_CTAS (D_SZ / BD)           // 20
#define STREAM_CTAS (5 * B_SZ * SPLITS)   // 840
#define TOTAL_CTAS (SERIES_CTAS + STREAM_CTAS) // 860 < 888 (148*6)
#define N_GROUPS (5 * B_SZ)               // 40

__device__ float4   g_part[SPLITS * B_SZ * D4_SZ];    // partial sums (3.44 MB)
__device__ float    g_emb [B_SZ * D_SZ];              // un-normalized projection
__device__ float    g_ssq_part[SERIES_CTAS * B_SZ];   // per-CTA per-batch sumsq
__device__ unsigned g_next[N_GROUPS];                 // per-group chunk cursor
__device__ unsigned g_cnt[N_GROUPS];                  // per-group arrival counters
__device__ unsigned g_series_done;                    // == 20 when series done
__device__ unsigned g_fin;                            // finisher count (reset)

__device__ __forceinline__ unsigned atom_add_acqrel_gpu(unsigned* p, unsigned v) {
    unsigned old;
    asm volatile("atom.add.acq_rel.gpu.u32 %0, [%1], %2;"
                 : "=r"(old) : "l"(p), "r"(v) : "memory");
    return old;
}
__device__ __forceinline__ unsigned ld_acquire_gpu(const unsigned* p) {
    unsigned v;
    asm volatile("ld.acquire.gpu.u32 %0, [%1];" : "=r"(v) : "l"(p) : "memory");
    return v;
}

__global__ __launch_bounds__(BD, 6) void fused_kernel(
    const float* __restrict__ hs,
    const float* __restrict__ x,
    const float* __restrict__ W,
    const float* __restrict__ bias,
    float* __restrict__ out_fused,
    float* __restrict__ out_xnorm)
{
    const int cta = blockIdx.x;
    const int tid = threadIdx.x;

    if (cta < SERIES_CTAS) {
        // ================= series branch (20 CTAs) ==========================
        const int sid = cta;
        const int d   = sid * BD + tid;

        __shared__ float sx[B_SZ * C_SZ * T_SZ];
        __shared__ float smn[B_SZ * C_SZ], smx[B_SZ * C_SZ];
        __shared__ float s_sm[B_SZ * T_SZ];
        __shared__ float sred[8][B_SZ];

        const int TOT = B_SZ * C_SZ * T_SZ;       // 2520
        for (int i = tid; i < TOT; i += BD) sx[i] = x[i];
        __syncthreads();

        if (tid < B_SZ * C_SZ) {
            const float* row = sx + tid * T_SZ;
            float mn = row[0], mx = row[0];
            #pragma unroll
            for (int t = 1; t < T_SZ; t++) {
                float v = row[t];
                mn = fminf(mn, v); mx = fmaxf(mx, v);
            }
            smn[tid] = mn; smx[tid] = mx;
        }
        __syncthreads();

        if (sid == 0) {
            for (int i = tid; i < TOT; i += BD) {
                int bc = i / T_SZ;
                float v = sx[i], mn = smn[bc], mx = smx[bc];
                out_xnorm[i] = (mx > mn) ? (v - mn) / (mx - mn) : v;
            }
        }

        for (int i = tid; i < B_SZ * T_SZ; i += BD) {
            int b = i / T_SZ, t = i % T_SZ;
            float s = 0.f;
            #pragma unroll
            for (int c = 0; c < C_SZ; c++)
                s += sx[(b * C_SZ + c) * T_SZ + t];
            s_sm[i] = s * (1.0f / (float)C_SZ);
        }
        __syncthreads();

        const float bv = bias[d];
        const int warp = tid >> 5, lane = tid & 31;

        #pragma unroll
        for (int g = 0; g < 2; g++) {
            float acc0 = bv, acc1 = bv, acc2 = bv, acc3 = bv;
            const float* m0 = s_sm + (g * 4 + 0) * T_SZ;
            const float* m1 = s_sm + (g * 4 + 1) * T_SZ;
            const float* m2 = s_sm + (g * 4 + 2) * T_SZ;
            const float* m3 = s_sm + (g * 4 + 3) * T_SZ;
            #pragma unroll
            for (int t = 0; t < T_SZ; t++) {
                const float w = W[(size_t)t * D_SZ + d];
                acc0 = fmaf(m0[t], w, acc0);
                acc1 = fmaf(m1[t], w, acc1);
                acc2 = fmaf(m2[t], w, acc2);
                acc3 = fmaf(m3[t], w, acc3);
            }
            g_emb[(size_t)(g * 4 + 0) * D_SZ + d] = acc0;
            g_emb[(size_t)(g * 4 + 1) * D_SZ + d] = acc1;
            g_emb[(size_t)(g * 4 + 2) * D_SZ + d] = acc2;
            g_emb[(size_t)(g * 4 + 3) * D_SZ + d] = acc3;

            const float sq[4] = {acc0 * acc0, acc1 * acc1, acc2 * acc2, acc3 * acc3};
            #pragma unroll
            for (int j = 0; j < 4; j++) {
                float v = sq[j];
                #pragma unroll
                for (int off = 16; off; off >>= 1)
                    v += __shfl_xor_sync(0xffffffffu, v, off);
                if (lane == 0) sred[warp][g * 4 + j] = v;
            }
            __syncthreads();
            if (tid < 4) {
                int b = g * 4 + tid;
                float tot = 0.f;
                #pragma unroll
                for (int w2 = 0; w2 < 8; w2++) tot += sred[w2][b];
                g_ssq_part[sid * B_SZ + b] = tot;
            }
            __syncthreads();
        }

        if (tid == 0) atom_add_acqrel_gpu(&g_series_done, 1u);
    } else {
        // ================= streaming CTAs (840, work-stealing) ==============
        const int scta   = cta - SERIES_CTAS;
        const int group  = scta % N_GROUPS;       // (b, dchunk)
        const int rank   = scta / N_GROUPS;       // 0..20: partial slot
        const int dchunk = group % 5;
        const int b      = group / 5;
        const int d4     = dchunk * BD + tid;

        const float4* base = reinterpret_cast<const float4*>(hs)
                           + (size_t)b * S_SZ * D4_SZ + d4;

        __shared__ unsigned s_chunk;

        float4 a0 = make_float4(0.f, 0.f, 0.f, 0.f);
        float4 a1 = make_float4(0.f, 0.f, 0.f, 0.f);

        for (;;) {
            if (tid == 0) s_chunk = atomicAdd(&g_next[group], 1u);
            __syncthreads();
            const unsigned ck = s_chunk;
            __syncthreads();                      // protect s_chunk reuse
            if (ck >= N_CHUNKS) break;

            const float4* p = base + (size_t)(ck * CHUNK_ROWS) * D4_SZ;
            #pragma unroll 4
            for (int r = 0; r < CHUNK_ROWS; r += 2) {
                float4 v0 = __ldcs(p + (size_t)(r + 0) * D4_SZ);
                float4 v1 = __ldcs(p + (size_t)(r + 1) * D4_SZ);
                a0.x += v0.x; a0.y += v0.y; a0.z += v0.z; a0.w += v0.w;
                a1.x += v1.x; a1.y += v1.y; a1.z += v1.z; a1.w += v1.w;
            }
        }

        float4 out;
        out.x = a0.x + a1.x; out.y = a0.y + a1.y;
        out.z = a0.z + a1.z; out.w = a0.w + a1.w;
        g_part[((size_t)rank * B_SZ + b) * D4_SZ + d4] = out;

        // arrival: intra-CTA order + release-bump by thread 0
        __shared__ bool s_last;
        __syncthreads();
        if (tid == 0) {
            unsigned old = atom_add_acqrel_gpu(&g_cnt[group], 1u);
            s_last = (old == SPLITS - 1);
        }
        __syncthreads();

        if (s_last) {
            // ---- finisher: reduce 21 partials for this (b, dchunk) --------
            __shared__ float s_inv;
            if (tid == 0) {
                while (ld_acquire_gpu(&g_series_done) < SERIES_CTAS)
                    __nanosleep(64);
                float ssq = 0.f;
                #pragma unroll
                for (int s = 0; s < SERIES_CTAS; s++)
                    ssq += __ldcg(&g_ssq_part[s * B_SZ + b]);
                s_inv = 1.0f / fmaxf(sqrtf(ssq), 1e-12f);
            }
            __syncthreads();

            const float4* gp = g_part + (size_t)b * D4_SZ + d4;
            float4 acc = make_float4(0.f, 0.f, 0.f, 0.f);
            #pragma unroll
            for (int rr = 0; rr < SPLITS; rr++) {
                float4 v = __ldcg(gp + (size_t)rr * (B_SZ * D4_SZ));
                acc.x += v.x; acc.y += v.y; acc.z += v.z; acc.w += v.w;
            }

            const float inv  = s_inv;
            const float invS = 1.0f / (float)S_SZ;
            const float* e = g_emb + (size_t)b * D_SZ + (size_t)d4 * 4;
            float e0 = __ldcg(e + 0), e1 = __ldcg(e + 1);
            float e2 = __ldcg(e + 2), e3 = __ldcg(e + 3);

            float4 o;
            o.x = fmaf(e0, inv, acc.x * invS);
            o.y = fmaf(e1, inv, acc.y * invS);
            o.z = fmaf(e2, inv, acc.z * invS);
            o.w = fmaf(e3, inv, acc.w * invS);
            reinterpret_cast<float4*>(out_fused)[(size_t)b * D4_SZ + d4] = o;

            // reset for next graph replay (kernel boundary orders visibility)
            __syncthreads();
            if (tid == 0) {
                g_cnt[group]  = 0u;
                g_next[group] = 0u;
                unsigned f = atom_add_acqrel_gpu(&g_fin, 1u);
                if (f == N_GROUPS - 1) {      // globally last finisher
                    g_series_done = 0u;
                    g_fin = 0u;
                }
            }
        }
    }
}

// ============================================================================
extern "C" void kernel_launch(void* const* d_in, const int* in_sizes, int n_in,
                              void* d_out, int out_size)
{
    const float* x    = (const float*)d_in[0];
    const float* hs   = (const float*)d_in[1];
    const float* W    = (const float*)d_in[2];
    const float* bias = (const float*)d_in[3];

    float* out_fused = (float*)d_out;                       // [B, D]
    float* out_xnorm = (float*)d_out + (size_t)B_SZ * D_SZ; // [B, C, T]

    fused_kernel<<<TOTAL_CTAS, BD>>>(hs, x, W, bias, out_fused, out_xnorm);
}

// round 11
// speedup vs baseline: 1.0974x; 1.0609x over previous
#include <cuda_runtime.h>
#include <math.h>

// ---------------------------------------------------------------------------
// TextEmbedderLETS on GB300 — R11: R10 work stealing with FINE chunks.
//   R10 bug: 64-row chunks -> 64 chunks / 21 CTAs = 3-vs-4 chunk imbalance
//   (33%!) -> ~5us ragged tail with only ~40 CTAs alive. Fix: 16-row chunks
//   (256/group, ~12 per CTA) -> residual imbalance = 1 chunk ~ 0.4%.
//   Single kernel (2nd kernel costs fixed ~4-5us, R4 vs R8 ledger).
// ---------------------------------------------------------------------------

#define BD 256
#define B_SZ 8
#define C_SZ 7
#define T_SZ 45
#define D_SZ 5120
#define D4_SZ (D_SZ / 4)          // 1280
#define S_SZ 4096
#define SPLITS 21                 // CTAs per group (partial slots)
#define CHUNK_ROWS 16
#define N_CHUNKS (S_SZ / CHUNK_ROWS)      // 256 chunks per group
#define SERIES_CTAS (D_SZ / BD)           // 20
#define STREAM_CTAS (5 * B_SZ * SPLITS)   // 840
#define TOTAL_CTAS (SERIES_CTAS + STREAM_CTAS) // 860 < 888 (148*6)
#define N_GROUPS (5 * B_SZ)               // 40

__device__ float4   g_part[SPLITS * B_SZ * D4_SZ];    // partial sums (3.44 MB)
__device__ float    g_emb [B_SZ * D_SZ];              // un-normalized projection
__device__ float    g_ssq_part[SERIES_CTAS * B_SZ];   // per-CTA per-batch sumsq
__device__ unsigned g_next[N_GROUPS];                 // per-group chunk cursor
__device__ unsigned g_cnt[N_GROUPS];                  // per-group arrival counters
__device__ unsigned g_series_done;                    // == 20 when series done
__device__ unsigned g_fin;                            // finisher count (reset)

__device__ __forceinline__ unsigned atom_add_acqrel_gpu(unsigned* p, unsigned v) {
    unsigned old;
    asm volatile("atom.add.acq_rel.gpu.u32 %0, [%1], %2;"
                 : "=r"(old) : "l"(p), "r"(v) : "memory");
    return old;
}
__device__ __forceinline__ unsigned ld_acquire_gpu(const unsigned* p) {
    unsigned v;
    asm volatile("ld.acquire.gpu.u32 %0, [%1];" : "=r"(v) : "l"(p) : "memory");
    return v;
}

__global__ __launch_bounds__(BD, 6) void fused_kernel(
    const float* __restrict__ hs,
    const float* __restrict__ x,
    const float* __restrict__ W,
    const float* __restrict__ bias,
    float* __restrict__ out_fused,
    float* __restrict__ out_xnorm)
{
    const int cta = blockIdx.x;
    const int tid = threadIdx.x;

    if (cta < SERIES_CTAS) {
        // ================= series branch (20 CTAs) ==========================
        const int sid = cta;
        const int d   = sid * BD + tid;

        __shared__ float sx[B_SZ * C_SZ * T_SZ];
        __shared__ float smn[B_SZ * C_SZ], smx[B_SZ * C_SZ];
        __shared__ float s_sm[B_SZ * T_SZ];
        __shared__ float sred[8][B_SZ];

        const int TOT = B_SZ * C_SZ * T_SZ;       // 2520
        for (int i = tid; i < TOT; i += BD) sx[i] = x[i];
        __syncthreads();

        if (tid < B_SZ * C_SZ) {
            const float* row = sx + tid * T_SZ;
            float mn = row[0], mx = row[0];
            #pragma unroll
            for (int t = 1; t < T_SZ; t++) {
                float v = row[t];
                mn = fminf(mn, v); mx = fmaxf(mx, v);
            }
            smn[tid] = mn; smx[tid] = mx;
        }
        __syncthreads();

        if (sid == 0) {
            for (int i = tid; i < TOT; i += BD) {
                int bc = i / T_SZ;
                float v = sx[i], mn = smn[bc], mx = smx[bc];
                out_xnorm[i] = (mx > mn) ? (v - mn) / (mx - mn) : v;
            }
        }

        for (int i = tid; i < B_SZ * T_SZ; i += BD) {
            int b = i / T_SZ, t = i % T_SZ;
            float s = 0.f;
            #pragma unroll
            for (int c = 0; c < C_SZ; c++)
                s += sx[(b * C_SZ + c) * T_SZ + t];
            s_sm[i] = s * (1.0f / (float)C_SZ);
        }
        __syncthreads();

        const float bv = bias[d];
        const int warp = tid >> 5, lane = tid & 31;

        #pragma unroll
        for (int g = 0; g < 2; g++) {
            float acc0 = bv, acc1 = bv, acc2 = bv, acc3 = bv;
            const float* m0 = s_sm + (g * 4 + 0) * T_SZ;
            const float* m1 = s_sm + (g * 4 + 1) * T_SZ;
            const float* m2 = s_sm + (g * 4 + 2) * T_SZ;
            const float* m3 = s_sm + (g * 4 + 3) * T_SZ;
            #pragma unroll
            for (int t = 0; t < T_SZ; t++) {
                const float w = W[(size_t)t * D_SZ + d];
                acc0 = fmaf(m0[t], w, acc0);
                acc1 = fmaf(m1[t], w, acc1);
                acc2 = fmaf(m2[t], w, acc2);
                acc3 = fmaf(m3[t], w, acc3);
            }
            g_emb[(size_t)(g * 4 + 0) * D_SZ + d] = acc0;
            g_emb[(size_t)(g * 4 + 1) * D_SZ + d] = acc1;
            g_emb[(size_t)(g * 4 + 2) * D_SZ + d] = acc2;
            g_emb[(size_t)(g * 4 + 3) * D_SZ + d] = acc3;

            const float sq[4] = {acc0 * acc0, acc1 * acc1, acc2 * acc2, acc3 * acc3};
            #pragma unroll
            for (int j = 0; j < 4; j++) {
                float v = sq[j];
                #pragma unroll
                for (int off = 16; off; off >>= 1)
                    v += __shfl_xor_sync(0xffffffffu, v, off);
                if (lane == 0) sred[warp][g * 4 + j] = v;
            }
            __syncthreads();
            if (tid < 4) {
                int b = g * 4 + tid;
                float tot = 0.f;
                #pragma unroll
                for (int w2 = 0; w2 < 8; w2++) tot += sred[w2][b];
                g_ssq_part[sid * B_SZ + b] = tot;
            }
            __syncthreads();
        }

        if (tid == 0) atom_add_acqrel_gpu(&g_series_done, 1u);
    } else {
        // ================= streaming CTAs (840, fine-grain stealing) ========
        const int scta   = cta - SERIES_CTAS;
        const int group  = scta % N_GROUPS;       // (b, dchunk)
        const int rank   = scta / N_GROUPS;       // 0..20: partial slot
        const int dchunk = group % 5;
        const int b      = group / 5;
        const int d4     = dchunk * BD + tid;

        const float4* base = reinterpret_cast<const float4*>(hs)
                           + (size_t)b * S_SZ * D4_SZ + d4;

        __shared__ unsigned s_chunk;

        float4 a0 = make_float4(0.f, 0.f, 0.f, 0.f);
        float4 a1 = make_float4(0.f, 0.f, 0.f, 0.f);

        for (;;) {
            if (tid == 0) s_chunk = atomicAdd(&g_next[group], 1u);
            __syncthreads();
            const unsigned ck = s_chunk;
            __syncthreads();                      // protect s_chunk reuse
            if (ck >= N_CHUNKS) break;

            const float4* p = base + (size_t)(ck * CHUNK_ROWS) * D4_SZ;
            #pragma unroll
            for (int r = 0; r < CHUNK_ROWS; r += 2) {
                float4 v0 = __ldcs(p + (size_t)(r + 0) * D4_SZ);
                float4 v1 = __ldcs(p + (size_t)(r + 1) * D4_SZ);
                a0.x += v0.x; a0.y += v0.y; a0.z += v0.z; a0.w += v0.w;
                a1.x += v1.x; a1.y += v1.y; a1.z += v1.z; a1.w += v1.w;
            }
        }

        float4 out;
        out.x = a0.x + a1.x; out.y = a0.y + a1.y;
        out.z = a0.z + a1.z; out.w = a0.w + a1.w;
        g_part[((size_t)rank * B_SZ + b) * D4_SZ + d4] = out;

        // arrival: intra-CTA order + release-bump by thread 0
        __shared__ bool s_last;
        __syncthreads();
        if (tid == 0) {
            unsigned old = atom_add_acqrel_gpu(&g_cnt[group], 1u);
            s_last = (old == SPLITS - 1);
        }
        __syncthreads();

        if (s_last) {
            // ---- finisher: reduce 21 partials for this (b, dchunk) --------
            __shared__ float s_inv;
            if (tid == 0) {
                while (ld_acquire_gpu(&g_series_done) < SERIES_CTAS)
                    __nanosleep(64);
                float ssq = 0.f;
                #pragma unroll
                for (int s = 0; s < SERIES_CTAS; s++)
                    ssq += __ldcg(&g_ssq_part[s * B_SZ + b]);
                s_inv = 1.0f / fmaxf(sqrtf(ssq), 1e-12f);
            }
            __syncthreads();

            const float4* gp = g_part + (size_t)b * D4_SZ + d4;
            float4 acc = make_float4(0.f, 0.f, 0.f, 0.f);
            #pragma unroll
            for (int rr = 0; rr < SPLITS; rr++) {
                float4 v = __ldcg(gp + (size_t)rr * (B_SZ * D4_SZ));
                acc.x += v.x; acc.y += v.y; acc.z += v.z; acc.w += v.w;
            }

            const float inv  = s_inv;
            const float invS = 1.0f / (float)S_SZ;
            const float* e = g_emb + (size_t)b * D_SZ + (size_t)d4 * 4;
            float e0 = __ldcg(e + 0), e1 = __ldcg(e + 1);
            float e2 = __ldcg(e + 2), e3 = __ldcg(e + 3);

            float4 o;
            o.x = fmaf(e0, inv, acc.x * invS);
            o.y = fmaf(e1, inv, acc.y * invS);
            o.z = fmaf(e2, inv, acc.z * invS);
            o.w = fmaf(e3, inv, acc.w * invS);
            reinterpret_cast<float4*>(out_fused)[(size_t)b * D4_SZ + d4] = o;

            // reset for next graph replay (kernel boundary orders visibility)
            __syncthreads();
            if (tid == 0) {
                g_cnt[group]  = 0u;
                g_next[group] = 0u;
                unsigned f = atom_add_acqrel_gpu(&g_fin, 1u);
                if (f == N_GROUPS - 1) {      // globally last finisher
                    g_series_done = 0u;
                    g_fin = 0u;
                }
            }
        }
    }
}

// ============================================================================
extern "C" void kernel_launch(void* const* d_in, const int* in_sizes, int n_in,
                              void* d_out, int out_size)
{
    const float* x    = (const float*)d_in[0];
    const float* hs   = (const float*)d_in[1];
    const float* W    = (const float*)d_in[2];
    const float* bias = (const float*)d_in[3];

    float* out_fused = (float*)d_out;                       // [B, D]
    float* out_xnorm = (float*)d_out + (size_t)B_SZ * D_SZ; // [B, C, T]

    fused_kernel<<<TOTAL_CTAS, BD>>>(hs, x, W, bias, out_fused, out_xnorm);
}